// round 14
// baseline (speedup 1.0000x reference)
#include <cuda_runtime.h>
#include <cuda_bf16.h>
#include <cstdint>
#include <math.h>

// ---------------------------------------------------------------------------
// MPNN on GB300 (round 14).
//  - All A-side feature buffers stored with a 4-bit column rotation
//    PERM(c) = (c&48)|((c<<2)&12)|((c>>2)&3) (involution). Under this layout
//    the mma.sync A-fragments for two consecutive k-steps are ONE float4 load
//    (was 8 scalar LDGs): L1 wavefronts on the layer kernel drop ~4x.
//  - msgbuf pitch 80 (conflict-free LDS.128 fragment reads).
//  - Rest = round-13 pipeline (padded CSR, unroll-8 gathers, fused readout).
// ---------------------------------------------------------------------------

#define MAXN 65536
#define MAXG 512
#define FD   64
#define SLOT 96
#define MSGP 80

#define PERM(c) ((((c) & 48)) | (((c) << 2) & 12) | (((c) >> 2) & 3))

typedef unsigned long long ull;

__device__ int   g_deg[MAXN];
__device__ int   g_srcpad[MAXN * SLOT];
__device__ int   g_degmax;

__device__ float g_h[MAXN * FD];
__device__ float g_nagg[MAXN * FD];
__device__ float g_naggH[MAXN * FD];
__device__ float g_eemb[MAXN * FD];
__device__ float g_curA[MAXN * FD];
__device__ float g_curB[MAXN * FD];

__device__ float g_means[MAXG * FD];
__device__ float g_cnt[MAXG];
__device__ float g_gconst[MAXG];

// ----------------------------- helpers ------------------------------------
__device__ __forceinline__ uint32_t tf32r(float x) {
    uint32_t y;
    asm("cvt.rna.tf32.f32 %0, %1;" : "=r"(y) : "f"(x));
    return y;
}

__device__ __forceinline__ void mma_tf32(float acc[4], uint32_t a0, uint32_t a1,
                                         uint32_t a2, uint32_t a3,
                                         uint32_t b0, uint32_t b1) {
    asm volatile("mma.sync.aligned.m16n8k8.row.col.f32.tf32.tf32.f32 "
                 "{%0,%1,%2,%3}, {%4,%5,%6,%7}, {%8,%9}, {%0,%1,%2,%3};"
                 : "+f"(acc[0]), "+f"(acc[1]), "+f"(acc[2]), "+f"(acc[3])
                 : "r"(a0), "r"(a1), "r"(a2), "r"(a3), "r"(b0), "r"(b1));
}

// ----------------------------- structure build -----------------------------
__global__ void k_fillpad(const int* __restrict__ row, const int* __restrict__ col,
                          const float* __restrict__ x, const float* __restrict__ Wi,
                          const float* __restrict__ We1, int E, int n, int nobs) {
    int i = blockIdx.x * blockDim.x + threadIdx.x;
    if (i < E) {
        int c = col[i];
        int p = atomicAdd(&g_deg[c], 1);
        if (p < SLOT) g_srcpad[c * SLOT + p] = row[i];
    } else {
        int t = i - E;
        if (t >= n * 64) return;
        int node = t >> 6, c = t & 63;
        const float* xr = x + node * nobs;
        float s1 = 0.f, s2 = 0.f;
        for (int j = 0; j < nobs; j++) {
            float xv = __ldg(&xr[j]);
            s1 += xv * __ldg(&Wi[j * 64 + c]);
            if (c < 63) s2 += xv * __ldg(&We1[j * 63 + c]);
        }
        int pc = PERM(c);
        g_curA[node * 64 + pc] = fmaxf(s1, 0.f);
        g_h[node * 64 + pc]    = (c < 63) ? fmaxf(s2, 0.f) : 0.f;
    }
}

// gathers are elementwise means over rows -> permutation-transparent
__global__ void k_dgather(const float* __restrict__ h, const float* __restrict__ cur,
                          float* __restrict__ outH, float* __restrict__ outC, int n) {
    __shared__ int ssmax;
    int tid = threadIdx.x;
    if (tid == 0) ssmax = 0;
    __syncthreads();

    int hw = (blockIdx.x * blockDim.x + tid) >> 4;
    int lane = tid & 15;
    bool valid = (hw < n);
    int d = valid ? g_deg[hw] : 0;
    int dc = min(d, SLOT);
    int base = hw * SLOT;
    const float4* h4 = (const float4*)h;
    const float4* c4 = (const float4*)cur;
    float hx = 0.f, hy = 0.f, hz = 0.f, hw_ = 0.f;
    float cx = 0.f, cy = 0.f, cz = 0.f, cw = 0.f;
    int i = 0;
    for (; i + 8 <= dc; i += 8) {
        int s[8];
#pragma unroll
        for (int u = 0; u < 8; u++) s[u] = __ldg(&g_srcpad[base + i + u]);
        float4 a[8], b[8];
#pragma unroll
        for (int u = 0; u < 8; u++) {
            a[u] = __ldg(&h4[s[u] * 16 + lane]);
            b[u] = __ldg(&c4[s[u] * 16 + lane]);
        }
#pragma unroll
        for (int u = 0; u < 8; u++) {
            hx += a[u].x; hy += a[u].y; hz += a[u].z; hw_ += a[u].w;
            cx += b[u].x; cy += b[u].y; cz += b[u].z; cw += b[u].w;
        }
    }
    for (; i < dc; i++) {
        int s = __ldg(&g_srcpad[base + i]);
        float4 a = __ldg(&h4[s * 16 + lane]);
        float4 b = __ldg(&c4[s * 16 + lane]);
        hx += a.x; hy += a.y; hz += a.z; hw_ += a.w;
        cx += b.x; cy += b.y; cz += b.z; cw += b.w;
    }
    if (valid) {
        float sc = (d > 0) ? (1.0f / (float)d) : 0.0f;
        hx *= sc; hy *= sc; hz *= sc; hw_ *= sc;
        cx *= sc; cy *= sc; cz *= sc; cw *= sc;
        if (lane == 15) hw_ = 0.f;   // position 63 == orig col 63; patched in k_gemm64
        ((float4*)outH)[hw * 16 + lane] = make_float4(hx, hy, hz, hw_);
        ((float4*)outC)[hw * 16 + lane] = make_float4(cx, cy, cz, cw);
    }
    if (lane == 0 && valid) atomicMax(&ssmax, d);
    __syncthreads();
    if (tid == 0) atomicMax(&g_degmax, ssmax);
}

__global__ void k_gather(const float* __restrict__ feat, float* __restrict__ out, int n) {
    int hw = (blockIdx.x * blockDim.x + threadIdx.x) >> 4;
    int lane = threadIdx.x & 15;
    if (hw >= n) return;
    int d = g_deg[hw];
    int dc = min(d, SLOT);
    int base = hw * SLOT;
    const float4* f4 = (const float4*)feat;
    float ax = 0.f, ay = 0.f, az = 0.f, aw = 0.f;
    int i = 0;
    for (; i + 8 <= dc; i += 8) {
        int s[8];
#pragma unroll
        for (int u = 0; u < 8; u++) s[u] = __ldg(&g_srcpad[base + i + u]);
        float4 v[8];
#pragma unroll
        for (int u = 0; u < 8; u++) v[u] = __ldg(&f4[s[u] * 16 + lane]);
#pragma unroll
        for (int u = 0; u < 8; u++) {
            ax += v[u].x; ay += v[u].y; az += v[u].z; aw += v[u].w;
        }
    }
    for (; i < dc; i++) {
        int s = __ldg(&g_srcpad[base + i]);
        float4 v = __ldg(&f4[s * 16 + lane]);
        ax += v.x; ay += v.y; az += v.z; aw += v.w;
    }
    float sc = (d > 0) ? (1.0f / (float)d) : 0.0f;
    ((float4*)out)[hw * 16 + lane] = make_float4(ax * sc, ay * sc, az * sc, aw * sc);
}

// ----------------------------- mma.sync layer -------------------------------
// Bf layout unchanged: fragments carry ORIGINAL W rows (only A addresses move).
__device__ __forceinline__ void stage_Bf(float* __restrict__ Bf,
                                         const float* __restrict__ W, int tid) {
    for (int slot = tid; slot < 512; slot += 256) {
        int s = slot >> 5, l = slot & 31;
        int kr0 = 8 * s + (l & 3);
        int nc  = (l >> 2);
        float* dst = &Bf[slot * 20];
#pragma unroll
        for (int j = 0; j < 8; j++) {
            dst[2 * j]     = __uint_as_float(tf32r(__ldg(&W[(size_t)kr0 * 64 + nc + 8 * j])));
            dst[2 * j + 1] = __uint_as_float(tf32r(__ldg(&W[(size_t)(kr0 + 4) * 64 + nc + 8 * j])));
        }
    }
}

__device__ __forceinline__ void mma_step8(float acc[8][4], uint32_t A0, uint32_t A1,
                                          uint32_t A2, uint32_t A3,
                                          const float* __restrict__ Bf, int s, int l) {
    const uint4* bp = (const uint4*)&Bf[(s * 32 + l) * 20];
    uint4 b0 = bp[0], b1 = bp[1], b2 = bp[2], b3 = bp[3];
    mma_tf32(acc[0], A0, A1, A2, A3, b0.x, b0.y);
    mma_tf32(acc[1], A0, A1, A2, A3, b0.z, b0.w);
    mma_tf32(acc[2], A0, A1, A2, A3, b1.x, b1.y);
    mma_tf32(acc[3], A0, A1, A2, A3, b1.z, b1.w);
    mma_tf32(acc[4], A0, A1, A2, A3, b2.x, b2.y);
    mma_tf32(acc[5], A0, A1, A2, A3, b2.z, b2.w);
    mma_tf32(acc[6], A0, A1, A2, A3, b3.x, b3.y);
    mma_tf32(acc[7], A0, A1, A2, A3, b3.z, b3.w);
}

__device__ __forceinline__ float4 ld4g(const float* __restrict__ src, int node,
                                       int off, int n) {
    return (node < n) ? __ldg((const float4*)&src[(size_t)node * 64 + off])
                      : make_float4(0.f, 0.f, 0.f, 0.f);
}

template <bool LAST>
__global__ __launch_bounds__(256) void k_layer_mma(const float* __restrict__ nagg,
                                                   const float* __restrict__ eemb,
                                                   const float* __restrict__ cur,
                                                   const float* __restrict__ Wmsg,
                                                   const float* __restrict__ Wupd,
                                                   float* __restrict__ cout,
                                                   const float* __restrict__ Wr,
                                                   const int* __restrict__ batch,
                                                   float* __restrict__ out, int n) {
    extern __shared__ float sm[];
    float* Bf     = sm;            // 512*20 floats (40KB)
    float* msgbuf = sm + 10240;    // 128*MSGP floats (40KB)
    __shared__ float Wrs[64];

    int tid = threadIdx.x;
    int w = tid >> 5;
    int l = tid & 31;
    int lg = l >> 2;
    int lq = l & 3;
    int r0 = 16 * w + lg;
    int node0 = blockIdx.x * 128;
    int nodeA = node0 + r0;
    int nodeB = node0 + r0 + 8;

    if (LAST && tid < 64) Wrs[tid] = __ldg(&Wr[64 + tid]);
    stage_Bf(Bf, Wmsg, tid);
    __syncthreads();

    float acc[8][4];
#pragma unroll
    for (int j = 0; j < 8; j++)
#pragma unroll
        for (int m = 0; m < 4; m++) acc[j][m] = 0.f;

    // ---- phase 1: msg = relu( concat(nagg, eemb) @ Wmsg )
    // s-pair sp covers k-steps (2sp, 2sp+1); permuted layout makes each pair
    // one float4 per row: [a0(2sp), a2(2sp), a0(2sp+1), a2(2sp+1)]
#pragma unroll
    for (int sp = 0; sp < 8; sp++) {
        const float* src = (sp < 4) ? nagg : eemb;
        int off = ((sp & 3) << 4) + 4 * lq;
        float4 va = ld4g(src, nodeA, off, n);
        float4 vb = ld4g(src, nodeB, off, n);
        mma_step8(acc, tf32r(va.x), tf32r(vb.x), tf32r(va.y), tf32r(vb.y), Bf, 2 * sp, l);
        mma_step8(acc, tf32r(va.z), tf32r(vb.z), tf32r(va.w), tf32r(vb.w), Bf, 2 * sp + 1, l);
    }

    // relu(msg) -> msgbuf at PERMUTED positions (it is next phase's A input)
#pragma unroll
    for (int j = 0; j < 8; j++) {
        int oc0 = 8 * j + 2 * lq;
        int p0 = PERM(oc0), p1 = PERM(oc0 + 1);
        msgbuf[r0 * MSGP + p0]       = fmaxf(acc[j][0], 0.f);
        msgbuf[r0 * MSGP + p1]       = fmaxf(acc[j][1], 0.f);
        msgbuf[(r0 + 8) * MSGP + p0] = fmaxf(acc[j][2], 0.f);
        msgbuf[(r0 + 8) * MSGP + p1] = fmaxf(acc[j][3], 0.f);
    }
    __syncthreads();
    stage_Bf(Bf, Wupd, tid);
#pragma unroll
    for (int j = 0; j < 8; j++)
#pragma unroll
        for (int m = 0; m < 4; m++) acc[j][m] = 0.f;
    __syncthreads();

    // ---- phase 2: cout = relu( concat(cur, msg) @ Wupd )
#pragma unroll
    for (int sp = 0; sp < 4; sp++) {
        int off = (sp << 4) + 4 * lq;
        float4 va = ld4g(cur, nodeA, off, n);
        float4 vb = ld4g(cur, nodeB, off, n);
        mma_step8(acc, tf32r(va.x), tf32r(vb.x), tf32r(va.y), tf32r(vb.y), Bf, 2 * sp, l);
        mma_step8(acc, tf32r(va.z), tf32r(vb.z), tf32r(va.w), tf32r(vb.w), Bf, 2 * sp + 1, l);
    }
#pragma unroll
    for (int sp = 0; sp < 4; sp++) {
        int off = (sp << 4) + 4 * lq;
        float4 va = *(const float4*)&msgbuf[r0 * MSGP + off];
        float4 vb = *(const float4*)&msgbuf[(r0 + 8) * MSGP + off];
        mma_step8(acc, tf32r(va.x), tf32r(vb.x), tf32r(va.y), tf32r(vb.y), Bf, 8 + 2 * sp, l);
        mma_step8(acc, tf32r(va.z), tf32r(vb.z), tf32r(va.w), tf32r(vb.w), Bf, 9 + 2 * sp, l);
    }

    if (!LAST) {
        // cout is next layer's cur (A-side) -> write permuted
#pragma unroll
        for (int j = 0; j < 8; j++) {
            int oc0 = 8 * j + 2 * lq;
            int p0 = PERM(oc0), p1 = PERM(oc0 + 1);
            if (nodeA < n) {
                cout[(size_t)nodeA * 64 + p0] = fmaxf(acc[j][0], 0.f);
                cout[(size_t)nodeA * 64 + p1] = fmaxf(acc[j][1], 0.f);
            }
            if (nodeB < n) {
                cout[(size_t)nodeB * 64 + p0] = fmaxf(acc[j][2], 0.f);
                cout[(size_t)nodeB * 64 + p1] = fmaxf(acc[j][3], 0.f);
            }
        }
    } else {
        float dv0 = 0.f, dv1 = 0.f;
#pragma unroll
        for (int j = 0; j < 8; j++) {
            int c = 8 * j + 2 * lq;
            float w0 = Wrs[c], w1 = Wrs[c + 1];
            dv0 += fmaxf(acc[j][0], 0.f) * w0 + fmaxf(acc[j][1], 0.f) * w1;
            dv1 += fmaxf(acc[j][2], 0.f) * w0 + fmaxf(acc[j][3], 0.f) * w1;
        }
        dv0 += __shfl_xor_sync(0xffffffffu, dv0, 1);
        dv0 += __shfl_xor_sync(0xffffffffu, dv0, 2);
        dv1 += __shfl_xor_sync(0xffffffffu, dv1, 1);
        dv1 += __shfl_xor_sync(0xffffffffu, dv1, 2);
        if (lq == 0) {
            if (nodeA < n) out[nodeA] = dv0;
            if (nodeB < n) out[nodeB] = dv1;
        }
        // natural-order scratch for the per-graph segmented reduce
        __syncthreads();
#pragma unroll
        for (int j = 0; j < 8; j++) {
            int c = 8 * j + 2 * lq;
            *(float2*)&msgbuf[r0 * MSGP + c] =
                make_float2(fmaxf(acc[j][0], 0.f), fmaxf(acc[j][1], 0.f));
            *(float2*)&msgbuf[(r0 + 8) * MSGP + c] =
                make_float2(fmaxf(acc[j][2], 0.f), fmaxf(acc[j][3], 0.f));
        }
        __syncthreads();
        if (tid < 64) {
            int c = tid;
            float acc2 = 0.f, cnt = 0.f;
            int curb = -1;
            for (int i = 0; i < 128; i++) {
                int nd = node0 + i;
                if (nd >= n) break;
                int b = __ldg(&batch[nd]);
                if (b != curb) {
                    if (curb >= 0) {
                        atomicAdd(&g_means[curb * 64 + c], acc2);
                        if (c == 0) atomicAdd(&g_cnt[curb], cnt);
                    }
                    acc2 = 0.f; cnt = 0.f; curb = b;
                }
                acc2 += msgbuf[i * MSGP + c];
                cnt += 1.f;
            }
            if (curb >= 0) {
                atomicAdd(&g_means[curb * 64 + c], acc2);
                if (c == 0) atomicAdd(&g_cnt[curb], cnt);
            }
        }
    }
}

// ------------------------- FFMA2 GEMM (edge embedding) ---------------------
template <int K, int PITCH>
__device__ __forceinline__ void gemm_core8x8(const float* __restrict__ ins,
                                             const float* __restrict__ Ws,
                                             ull acc[8][4]) {
    int q  = threadIdx.x & 7;
    int rr = threadIdx.x >> 3;
#pragma unroll
    for (int j = 0; j < 8; j++)
#pragma unroll
        for (int m = 0; m < 4; m++) acc[j][m] = 0ull;

#pragma unroll 1
    for (int k = 0; k < K; k += 4) {
        float4 a[8];
#pragma unroll
        for (int j = 0; j < 8; j++)
            a[j] = *(const float4*)&ins[(rr + 16 * j) * PITCH + k];
#pragma unroll
        for (int kk = 0; kk < 4; kk++) {
            ulonglong2 w = *(const ulonglong2*)&Ws[(k + kk) * 64 + q * 8];
            ulonglong2 w2 = *(const ulonglong2*)&Ws[(k + kk) * 64 + q * 8 + 4];
#pragma unroll
            for (int j = 0; j < 8; j++) {
                float av = (kk == 0) ? a[j].x : (kk == 1) ? a[j].y
                         : (kk == 2) ? a[j].z : a[j].w;
                ull p;
                asm("mov.b64 %0, {%1, %1};" : "=l"(p) : "f"(av));
                asm("fma.rn.f32x2 %0, %1, %2, %0;" : "+l"(acc[j][0]) : "l"(p), "l"(w.x));
                asm("fma.rn.f32x2 %0, %1, %2, %0;" : "+l"(acc[j][1]) : "l"(p), "l"(w.y));
                asm("fma.rn.f32x2 %0, %1, %2, %0;" : "+l"(acc[j][2]) : "l"(p), "l"(w2.x));
                asm("fma.rn.f32x2 %0, %1, %2, %0;" : "+l"(acc[j][3]) : "l"(p), "l"(w2.y));
            }
        }
    }
}

// eemb = relu( naggH @ We2 ).  Input naggH is permuted -> stage Ws with
// PERM'd row order; output eemb written at PERM'd positions (A-side buffer).
__global__ __launch_bounds__(128) void k_gemm64(const float* __restrict__ A,
                                                const float* __restrict__ W,
                                                float* __restrict__ C, int n) {
    extern __shared__ float sm[];
    const int PITCH = 68;
    float* Ws  = sm;
    float* ins = sm + 64 * 64;
    int tid = threadIdx.x;
    int node0 = blockIdx.x * 128;
    float dmx = (float)max(g_degmax, 1);

    for (int idx = tid; idx < 64 * 16; idx += 128) {
        int p = idx >> 4, c4 = (idx & 15) << 2;
        *(float4*)&Ws[p * 64 + c4] = __ldg((const float4*)&W[(size_t)PERM(p) * 64 + c4]);
    }
    for (int idx = tid; idx < 2048; idx += 128) {
        int r = idx >> 4, c4 = (idx & 15) << 2;
        int node = node0 + r;
        float4 va = make_float4(0.f, 0.f, 0.f, 0.f);
        if (node < n) {
            va = __ldg((const float4*)&A[(size_t)node * 64 + c4]);
            if (c4 == 60) va.w = (float)g_deg[node] / dmx;   // position 63 == orig 63
        }
        *(float4*)&ins[r * PITCH + c4] = va;
    }
    __syncthreads();

    ull acc[8][4];
    gemm_core8x8<64, PITCH>(ins, Ws, acc);

    int q  = tid & 7;
    int rr = tid >> 3;
#pragma unroll
    for (int j = 0; j < 8; j++) {
        int node = node0 + rr + 16 * j;
        if (node < n) {
            float v[8];
#pragma unroll
            for (int m = 0; m < 4; m++) {
                float lo, hi;
                asm("mov.b64 {%0, %1}, %2;" : "=f"(lo), "=f"(hi) : "l"(acc[j][m]));
                v[2 * m] = fmaxf(lo, 0.f);
                v[2 * m + 1] = fmaxf(hi, 0.f);
            }
#pragma unroll
            for (int u = 0; u < 8; u++)
                C[(size_t)node * 64 + PERM(q * 8 + u)] = v[u];
        }
    }
}

// ------------------------------- readout -----------------------------------
__global__ void k_gconst(const float* __restrict__ Wp, const float* __restrict__ Wr,
                         const float* __restrict__ br) {
    int g = blockIdx.x;
    int t = threadIdx.x;
    __shared__ float m[64];
    __shared__ float red[64];
    float cnt = g_cnt[g];
    if (cnt <= 0.f) { if (t == 0) g_gconst[g] = 0.f; return; }
    m[t] = g_means[g * 64 + t] / cnt;
    __syncthreads();
    float p = 0.f;
#pragma unroll 8
    for (int k = 0; k < 64; k++) p += m[k] * __ldg(&Wp[k * 64 + t]);
    red[t] = fmaxf(p, 0.f) * __ldg(&Wr[t]);
    __syncthreads();
    if (t < 32) {
        float s = red[t] + red[t + 32];
#pragma unroll
        for (int off = 16; off > 0; off >>= 1) s += __shfl_down_sync(0xffffffffu, s, off);
        if (t == 0) g_gconst[g] = s + __ldg(&br[0]);
    }
}

__global__ void k_addg(const int* __restrict__ batch, float* __restrict__ out, int n) {
    int i = blockIdx.x * blockDim.x + threadIdx.x;
    if (i < n) out[i] += g_gconst[__ldg(&batch[i])];
}

// ---------------------------------------------------------------------------
extern "C" void kernel_launch(void* const* d_in, const int* in_sizes, int n_in,
                              void* d_out, int out_size) {
    const float* x    = (const float*)d_in[0];
    const float* Wi   = (const float*)d_in[1];
    const float* We1  = (const float*)d_in[2];
    const float* We2  = (const float*)d_in[3];
    const float* Wmsg = (const float*)d_in[4];
    const float* Wupd = (const float*)d_in[5];
    const float* Wp   = (const float*)d_in[6];
    const float* Wr   = (const float*)d_in[7];
    const float* br   = (const float*)d_in[8];
    const int*   eidx = (const int*)d_in[9];
    const int*   batch= (const int*)d_in[10];

    int n    = in_sizes[10];
    int E    = in_sizes[9] / 2;
    int nobs = in_sizes[0] / n;
    int L    = in_sizes[4] / (128 * 64);
    const int* row = eidx;
    const int* col = eidx + E;
    float* out = (float*)d_out;

    float *curA, *curB, *hbuf, *nagg, *naggH, *eemb, *means, *cnt;
    int *deg, *degmax;
    cudaGetSymbolAddress((void**)&curA, g_curA);
    cudaGetSymbolAddress((void**)&curB, g_curB);
    cudaGetSymbolAddress((void**)&hbuf, g_h);
    cudaGetSymbolAddress((void**)&nagg, g_nagg);
    cudaGetSymbolAddress((void**)&naggH, g_naggH);
    cudaGetSymbolAddress((void**)&eemb, g_eemb);
    cudaGetSymbolAddress((void**)&means, g_means);
    cudaGetSymbolAddress((void**)&cnt,   g_cnt);
    cudaGetSymbolAddress((void**)&deg,   g_deg);
    cudaGetSymbolAddress((void**)&degmax, g_degmax);

    const int SMEM_MMA = (10240 + 128 * MSGP) * 4;  // 40KB Bf + 40KB msgbuf
    const int SMEM64   = (64 * 64 + 128 * 68) * 4;
    cudaFuncSetAttribute(k_layer_mma<false>, cudaFuncAttributeMaxDynamicSharedMemorySize, SMEM_MMA);
    cudaFuncSetAttribute(k_layer_mma<true>,  cudaFuncAttributeMaxDynamicSharedMemorySize, SMEM_MMA);
    cudaFuncSetAttribute(k_layer_mma<false>, cudaFuncAttributePreferredSharedMemoryCarveout, 100);
    cudaFuncSetAttribute(k_layer_mma<true>,  cudaFuncAttributePreferredSharedMemoryCarveout, 100);
    cudaFuncSetAttribute(k_gemm64, cudaFuncAttributeMaxDynamicSharedMemorySize, SMEM64);

    int gFI = (E + n * 64 + 255) / 256;
    int gHW = (n * 16 + 255) / 256;
    int gG  = (n + 127) / 128;
    int gA  = (n + 255) / 256;

    cudaMemsetAsync(deg,    0, (size_t)n * sizeof(int));
    cudaMemsetAsync(degmax, 0, sizeof(int));
    cudaMemsetAsync(means,  0, (size_t)MAXG * FD * sizeof(float));
    cudaMemsetAsync(cnt,    0, (size_t)MAXG * sizeof(float));

    k_fillpad<<<gFI, 256>>>(row, col, x, Wi, We1, E, n, nobs);   // kernel 1
    k_dgather<<<gHW, 256>>>(hbuf, curA, naggH, nagg, n);         // kernel 2
    k_gemm64<<<gG, 128, SMEM64>>>(naggH, We2, eemb, n);          // kernel 3

    float* cin = curA;
    float* cout = curB;
    for (int l = 0; l < L; l++) {
        bool last = (l == L - 1);
        if (l > 0) k_gather<<<gHW, 256>>>(cin, nagg, n);
        if (!last) {
            k_layer_mma<false><<<gG, 256, SMEM_MMA>>>(nagg, eemb, cin,   // kernel 4 (l=0): profiled
                                                      Wmsg + (size_t)l * 8192,
                                                      Wupd + (size_t)l * 8192,
                                                      cout, nullptr, nullptr, nullptr, n);
            float* tmp = cin; cin = cout; cout = tmp;
        } else {
            k_layer_mma<true><<<gG, 256, SMEM_MMA>>>(nagg, eemb, cin,
                                                     Wmsg + (size_t)l * 8192,
                                                     Wupd + (size_t)l * 8192,
                                                     nullptr, Wr, batch, out, n);
        }
    }

    k_gconst<<<MAXG, 64>>>(Wp, Wr, br);
    k_addg<<<gA, 256>>>(batch, out, n);
}

// round 15
// speedup vs baseline: 1.0303x; 1.0303x over previous
#include <cuda_runtime.h>
#include <cuda_bf16.h>
#include <cstdint>
#include <math.h>

// ---------------------------------------------------------------------------
// MPNN on GB300 (round 15 = round 13 + Bf pitch-16 XOR swizzle).
//  - Bf shrunk 40KB -> 32KB via swizzled group placement (conflict-free
//    LDS.128 proven per 8-lane phase). smem/block 75776 -> 67584 B, which
//    clears the 8KB-granularity threshold: 2 -> 3 blocks/SM on k_layer_mma
//    (24 warps/SM, single wave for grid=391).
//  - Round-14's column permutation reverted (write-side scatter cost it).
//  - Rest = round-13: mma.sync tf32 layers, padded CSR, unroll-8 gathers,
//    fused readout.
// ---------------------------------------------------------------------------

#define MAXN 65536
#define MAXG 512
#define FD   64
#define SLOT 96
#define MSGP 68

typedef unsigned long long ull;

__device__ int   g_deg[MAXN];
__device__ int   g_srcpad[MAXN * SLOT];
__device__ int   g_degmax;

__device__ float g_h[MAXN * FD];
__device__ float g_nagg[MAXN * FD];
__device__ float g_naggH[MAXN * FD];
__device__ float g_eemb[MAXN * FD];
__device__ float g_curA[MAXN * FD];
__device__ float g_curB[MAXN * FD];

__device__ float g_means[MAXG * FD];
__device__ float g_cnt[MAXG];
__device__ float g_gconst[MAXG];

// ----------------------------- helpers ------------------------------------
__device__ __forceinline__ uint32_t tf32r(float x) {
    uint32_t y;
    asm("cvt.rna.tf32.f32 %0, %1;" : "=r"(y) : "f"(x));
    return y;
}

__device__ __forceinline__ void mma_tf32(float acc[4], uint32_t a0, uint32_t a1,
                                         uint32_t a2, uint32_t a3,
                                         uint32_t b0, uint32_t b1) {
    asm volatile("mma.sync.aligned.m16n8k8.row.col.f32.tf32.tf32.f32 "
                 "{%0,%1,%2,%3}, {%4,%5,%6,%7}, {%8,%9}, {%0,%1,%2,%3};"
                 : "+f"(acc[0]), "+f"(acc[1]), "+f"(acc[2]), "+f"(acc[3])
                 : "r"(a0), "r"(a1), "r"(a2), "r"(a3), "r"(b0), "r"(b1));
}

// ----------------------------- structure build -----------------------------
__global__ void k_fillpad(const int* __restrict__ row, const int* __restrict__ col,
                          const float* __restrict__ x, const float* __restrict__ Wi,
                          const float* __restrict__ We1, int E, int n, int nobs) {
    int i = blockIdx.x * blockDim.x + threadIdx.x;
    if (i < E) {
        int c = col[i];
        int p = atomicAdd(&g_deg[c], 1);
        if (p < SLOT) g_srcpad[c * SLOT + p] = row[i];
    } else {
        int t = i - E;
        if (t >= n * 64) return;
        int node = t >> 6, c = t & 63;
        const float* xr = x + node * nobs;
        float s1 = 0.f, s2 = 0.f;
        for (int j = 0; j < nobs; j++) {
            float xv = __ldg(&xr[j]);
            s1 += xv * __ldg(&Wi[j * 64 + c]);
            if (c < 63) s2 += xv * __ldg(&We1[j * 63 + c]);
        }
        g_curA[t] = fmaxf(s1, 0.f);
        g_h[t]    = (c < 63) ? fmaxf(s2, 0.f) : 0.f;
    }
}

__global__ void k_dgather(const float* __restrict__ h, const float* __restrict__ cur,
                          float* __restrict__ outH, float* __restrict__ outC, int n) {
    __shared__ int ssmax;
    int tid = threadIdx.x;
    if (tid == 0) ssmax = 0;
    __syncthreads();

    int hw = (blockIdx.x * blockDim.x + tid) >> 4;
    int lane = tid & 15;
    bool valid = (hw < n);
    int d = valid ? g_deg[hw] : 0;
    int dc = min(d, SLOT);
    int base = hw * SLOT;
    const float4* h4 = (const float4*)h;
    const float4* c4 = (const float4*)cur;
    float hx = 0.f, hy = 0.f, hz = 0.f, hw_ = 0.f;
    float cx = 0.f, cy = 0.f, cz = 0.f, cw = 0.f;
    int i = 0;
    for (; i + 8 <= dc; i += 8) {
        int s[8];
#pragma unroll
        for (int u = 0; u < 8; u++) s[u] = __ldg(&g_srcpad[base + i + u]);
        float4 a[8], b[8];
#pragma unroll
        for (int u = 0; u < 8; u++) {
            a[u] = __ldg(&h4[s[u] * 16 + lane]);
            b[u] = __ldg(&c4[s[u] * 16 + lane]);
        }
#pragma unroll
        for (int u = 0; u < 8; u++) {
            hx += a[u].x; hy += a[u].y; hz += a[u].z; hw_ += a[u].w;
            cx += b[u].x; cy += b[u].y; cz += b[u].z; cw += b[u].w;
        }
    }
    for (; i < dc; i++) {
        int s = __ldg(&g_srcpad[base + i]);
        float4 a = __ldg(&h4[s * 16 + lane]);
        float4 b = __ldg(&c4[s * 16 + lane]);
        hx += a.x; hy += a.y; hz += a.z; hw_ += a.w;
        cx += b.x; cy += b.y; cz += b.z; cw += b.w;
    }
    if (valid) {
        float sc = (d > 0) ? (1.0f / (float)d) : 0.0f;
        hx *= sc; hy *= sc; hz *= sc; hw_ *= sc;
        cx *= sc; cy *= sc; cz *= sc; cw *= sc;
        if (lane == 15) hw_ = 0.f;   // patched to deg/degmax in k_gemm64 staging
        ((float4*)outH)[hw * 16 + lane] = make_float4(hx, hy, hz, hw_);
        ((float4*)outC)[hw * 16 + lane] = make_float4(cx, cy, cz, cw);
    }
    if (lane == 0 && valid) atomicMax(&ssmax, d);
    __syncthreads();
    if (tid == 0) atomicMax(&g_degmax, ssmax);
}

__global__ void k_gather(const float* __restrict__ feat, float* __restrict__ out, int n) {
    int hw = (blockIdx.x * blockDim.x + threadIdx.x) >> 4;
    int lane = threadIdx.x & 15;
    if (hw >= n) return;
    int d = g_deg[hw];
    int dc = min(d, SLOT);
    int base = hw * SLOT;
    const float4* f4 = (const float4*)feat;
    float ax = 0.f, ay = 0.f, az = 0.f, aw = 0.f;
    int i = 0;
    for (; i + 8 <= dc; i += 8) {
        int s[8];
#pragma unroll
        for (int u = 0; u < 8; u++) s[u] = __ldg(&g_srcpad[base + i + u]);
        float4 v[8];
#pragma unroll
        for (int u = 0; u < 8; u++) v[u] = __ldg(&f4[s[u] * 16 + lane]);
#pragma unroll
        for (int u = 0; u < 8; u++) {
            ax += v[u].x; ay += v[u].y; az += v[u].z; aw += v[u].w;
        }
    }
    for (; i < dc; i++) {
        int s = __ldg(&g_srcpad[base + i]);
        float4 v = __ldg(&f4[s * 16 + lane]);
        ax += v.x; ay += v.y; az += v.z; aw += v.w;
    }
    float sc = (d > 0) ? (1.0f / (float)d) : 0.0f;
    ((float4*)out)[hw * 16 + lane] = make_float4(ax * sc, ay * sc, az * sc, aw * sc);
}

// ----------------------------- mma.sync layer -------------------------------
// Bf: pitch 16 floats (64B/slot), group g stored at (g ^ ((l>>1)&3))*16B.
// Per 8-lane LDS.128 phase: even lanes hit banks 4(g^{0..3}), odd lanes
// 16+4(g^{0..3}) -> conflict-free.
__device__ __forceinline__ void stage_Bf(float* __restrict__ Bf,
                                         const float* __restrict__ W, int tid) {
    for (int slot = tid; slot < 512; slot += 256) {
        int s = slot >> 5, l = slot & 31;
        int kr0 = 8 * s + (l & 3);
        int nc  = (l >> 2);
        int sw  = (l >> 1) & 3;
        float* dst = &Bf[slot * 16];
#pragma unroll
        for (int g = 0; g < 4; g++) {
            int go = 16 * g;
            float4 v;
            v.x = __uint_as_float(tf32r(__ldg(&W[(size_t)kr0 * 64 + nc + go])));
            v.y = __uint_as_float(tf32r(__ldg(&W[(size_t)(kr0 + 4) * 64 + nc + go])));
            v.z = __uint_as_float(tf32r(__ldg(&W[(size_t)kr0 * 64 + nc + go + 8])));
            v.w = __uint_as_float(tf32r(__ldg(&W[(size_t)(kr0 + 4) * 64 + nc + go + 8])));
            *(float4*)&dst[(g ^ sw) * 4] = v;
        }
    }
}

__device__ __forceinline__ uint32_t ldA(const float* __restrict__ src, int node,
                                        int c, int n) {
    return (node < n) ? tf32r(__ldg(&src[(size_t)node * 64 + c])) : 0u;
}

__device__ __forceinline__ void mma_step8(float acc[8][4], uint32_t A0, uint32_t A1,
                                          uint32_t A2, uint32_t A3,
                                          const float* __restrict__ Bf, int s, int l) {
    const float* base = &Bf[(s * 32 + l) * 16];
    int sw = (l >> 1) & 3;
    uint4 b0 = *(const uint4*)&base[(0 ^ sw) * 4];
    uint4 b1 = *(const uint4*)&base[(1 ^ sw) * 4];
    uint4 b2 = *(const uint4*)&base[(2 ^ sw) * 4];
    uint4 b3 = *(const uint4*)&base[(3 ^ sw) * 4];
    mma_tf32(acc[0], A0, A1, A2, A3, b0.x, b0.y);
    mma_tf32(acc[1], A0, A1, A2, A3, b0.z, b0.w);
    mma_tf32(acc[2], A0, A1, A2, A3, b1.x, b1.y);
    mma_tf32(acc[3], A0, A1, A2, A3, b1.z, b1.w);
    mma_tf32(acc[4], A0, A1, A2, A3, b2.x, b2.y);
    mma_tf32(acc[5], A0, A1, A2, A3, b2.z, b2.w);
    mma_tf32(acc[6], A0, A1, A2, A3, b3.x, b3.y);
    mma_tf32(acc[7], A0, A1, A2, A3, b3.z, b3.w);
}

template <bool LAST>
__global__ __launch_bounds__(256) void k_layer_mma(const float* __restrict__ nagg,
                                                   const float* __restrict__ eemb,
                                                   const float* __restrict__ cur,
                                                   const float* __restrict__ Wmsg,
                                                   const float* __restrict__ Wupd,
                                                   float* __restrict__ cout,
                                                   const float* __restrict__ Wr,
                                                   const int* __restrict__ batch,
                                                   float* __restrict__ out, int n) {
    extern __shared__ float sm[];
    float* Bf     = sm;           // 512*16 floats (32KB)
    float* msgbuf = sm + 8192;    // 128*68 floats (34KB)
    __shared__ float Wrs[64];

    int tid = threadIdx.x;
    int w = tid >> 5;
    int l = tid & 31;
    int lg = l >> 2;
    int lq = l & 3;
    int r0 = 16 * w + lg;
    int node0 = blockIdx.x * 128;

    if (LAST && tid < 64) Wrs[tid] = __ldg(&Wr[64 + tid]);
    stage_Bf(Bf, Wmsg, tid);
    __syncthreads();

    float acc[8][4];
#pragma unroll
    for (int j = 0; j < 8; j++)
#pragma unroll
        for (int m = 0; m < 4; m++) acc[j][m] = 0.f;

    // ---- phase 1: msg = relu( concat(nagg, eemb) @ Wmsg )
#pragma unroll 4
    for (int s = 0; s < 16; s++) {
        int c = 8 * s + lq;
        uint32_t a0, a1, a2, a3;
        if (s < 8) {
            a0 = ldA(nagg, node0 + r0, c, n);
            a1 = ldA(nagg, node0 + r0 + 8, c, n);
            a2 = ldA(nagg, node0 + r0, c + 4, n);
            a3 = ldA(nagg, node0 + r0 + 8, c + 4, n);
        } else {
            a0 = ldA(eemb, node0 + r0, c - 64, n);
            a1 = ldA(eemb, node0 + r0 + 8, c - 64, n);
            a2 = ldA(eemb, node0 + r0, c - 60, n);
            a3 = ldA(eemb, node0 + r0 + 8, c - 60, n);
        }
        mma_step8(acc, a0, a1, a2, a3, Bf, s, l);
    }

    // relu(msg) -> msgbuf
#pragma unroll
    for (int j = 0; j < 8; j++) {
        int c = 8 * j + 2 * lq;
        *(float2*)&msgbuf[r0 * MSGP + c] =
            make_float2(fmaxf(acc[j][0], 0.f), fmaxf(acc[j][1], 0.f));
        *(float2*)&msgbuf[(r0 + 8) * MSGP + c] =
            make_float2(fmaxf(acc[j][2], 0.f), fmaxf(acc[j][3], 0.f));
    }
    __syncthreads();
    stage_Bf(Bf, Wupd, tid);
#pragma unroll
    for (int j = 0; j < 8; j++)
#pragma unroll
        for (int m = 0; m < 4; m++) acc[j][m] = 0.f;
    __syncthreads();

    // ---- phase 2: cout = relu( concat(cur, msg) @ Wupd )
#pragma unroll 4
    for (int s = 0; s < 16; s++) {
        int c = 8 * s + lq;
        uint32_t a0, a1, a2, a3;
        if (s < 8) {
            a0 = ldA(cur, node0 + r0, c, n);
            a1 = ldA(cur, node0 + r0 + 8, c, n);
            a2 = ldA(cur, node0 + r0, c + 4, n);
            a3 = ldA(cur, node0 + r0 + 8, c + 4, n);
        } else {
            a0 = tf32r(msgbuf[r0 * MSGP + (c - 64)]);
            a1 = tf32r(msgbuf[(r0 + 8) * MSGP + (c - 64)]);
            a2 = tf32r(msgbuf[r0 * MSGP + (c - 60)]);
            a3 = tf32r(msgbuf[(r0 + 8) * MSGP + (c - 60)]);
        }
        mma_step8(acc, a0, a1, a2, a3, Bf, s, l);
    }

    if (!LAST) {
        int nodeA = node0 + r0;
        int nodeB = node0 + r0 + 8;
#pragma unroll
        for (int j = 0; j < 8; j++) {
            int c = 8 * j + 2 * lq;
            if (nodeA < n)
                *(float2*)&cout[(size_t)nodeA * 64 + c] =
                    make_float2(fmaxf(acc[j][0], 0.f), fmaxf(acc[j][1], 0.f));
            if (nodeB < n)
                *(float2*)&cout[(size_t)nodeB * 64 + c] =
                    make_float2(fmaxf(acc[j][2], 0.f), fmaxf(acc[j][3], 0.f));
        }
    } else {
        float dv0 = 0.f, dv1 = 0.f;
#pragma unroll
        for (int j = 0; j < 8; j++) {
            int c = 8 * j + 2 * lq;
            float w0 = Wrs[c], w1 = Wrs[c + 1];
            dv0 += fmaxf(acc[j][0], 0.f) * w0 + fmaxf(acc[j][1], 0.f) * w1;
            dv1 += fmaxf(acc[j][2], 0.f) * w0 + fmaxf(acc[j][3], 0.f) * w1;
        }
        dv0 += __shfl_xor_sync(0xffffffffu, dv0, 1);
        dv0 += __shfl_xor_sync(0xffffffffu, dv0, 2);
        dv1 += __shfl_xor_sync(0xffffffffu, dv1, 1);
        dv1 += __shfl_xor_sync(0xffffffffu, dv1, 2);
        if (lq == 0) {
            if (node0 + r0 < n)     out[node0 + r0]     = dv0;
            if (node0 + r0 + 8 < n) out[node0 + r0 + 8] = dv1;
        }
        __syncthreads();
#pragma unroll
        for (int j = 0; j < 8; j++) {
            int c = 8 * j + 2 * lq;
            *(float2*)&msgbuf[r0 * MSGP + c] =
                make_float2(fmaxf(acc[j][0], 0.f), fmaxf(acc[j][1], 0.f));
            *(float2*)&msgbuf[(r0 + 8) * MSGP + c] =
                make_float2(fmaxf(acc[j][2], 0.f), fmaxf(acc[j][3], 0.f));
        }
        __syncthreads();
        if (tid < 64) {
            int c = tid;
            float acc2 = 0.f, cnt = 0.f;
            int curb = -1;
            for (int i = 0; i < 128; i++) {
                int nd = node0 + i;
                if (nd >= n) break;
                int b = __ldg(&batch[nd]);
                if (b != curb) {
                    if (curb >= 0) {
                        atomicAdd(&g_means[curb * 64 + c], acc2);
                        if (c == 0) atomicAdd(&g_cnt[curb], cnt);
                    }
                    acc2 = 0.f; cnt = 0.f; curb = b;
                }
                acc2 += msgbuf[i * MSGP + c];
                cnt += 1.f;
            }
            if (curb >= 0) {
                atomicAdd(&g_means[curb * 64 + c], acc2);
                if (c == 0) atomicAdd(&g_cnt[curb], cnt);
            }
        }
    }
}

// ------------------------- FFMA2 GEMM (edge embedding) ---------------------
template <int K, int PITCH>
__device__ __forceinline__ void gemm_core8x8(const float* __restrict__ ins,
                                             const float* __restrict__ Ws,
                                             ull acc[8][4]) {
    int q  = threadIdx.x & 7;
    int rr = threadIdx.x >> 3;
#pragma unroll
    for (int j = 0; j < 8; j++)
#pragma unroll
        for (int m = 0; m < 4; m++) acc[j][m] = 0ull;

#pragma unroll 1
    for (int k = 0; k < K; k += 4) {
        float4 a[8];
#pragma unroll
        for (int j = 0; j < 8; j++)
            a[j] = *(const float4*)&ins[(rr + 16 * j) * PITCH + k];
#pragma unroll
        for (int kk = 0; kk < 4; kk++) {
            ulonglong2 w = *(const ulonglong2*)&Ws[(k + kk) * 64 + q * 8];
            ulonglong2 w2 = *(const ulonglong2*)&Ws[(k + kk) * 64 + q * 8 + 4];
#pragma unroll
            for (int j = 0; j < 8; j++) {
                float av = (kk == 0) ? a[j].x : (kk == 1) ? a[j].y
                         : (kk == 2) ? a[j].z : a[j].w;
                ull p;
                asm("mov.b64 %0, {%1, %1};" : "=l"(p) : "f"(av));
                asm("fma.rn.f32x2 %0, %1, %2, %0;" : "+l"(acc[j][0]) : "l"(p), "l"(w.x));
                asm("fma.rn.f32x2 %0, %1, %2, %0;" : "+l"(acc[j][1]) : "l"(p), "l"(w.y));
                asm("fma.rn.f32x2 %0, %1, %2, %0;" : "+l"(acc[j][2]) : "l"(p), "l"(w2.x));
                asm("fma.rn.f32x2 %0, %1, %2, %0;" : "+l"(acc[j][3]) : "l"(p), "l"(w2.y));
            }
        }
    }
}

__device__ __forceinline__ float4 acc_relu4(ull a0, ull a1) {
    float lo0, hi0, lo1, hi1;
    asm("mov.b64 {%0, %1}, %2;" : "=f"(lo0), "=f"(hi0) : "l"(a0));
    asm("mov.b64 {%0, %1}, %2;" : "=f"(lo1), "=f"(hi1) : "l"(a1));
    float4 o;
    o.x = fmaxf(lo0, 0.f); o.y = fmaxf(hi0, 0.f);
    o.z = fmaxf(lo1, 0.f); o.w = fmaxf(hi1, 0.f);
    return o;
}

// eemb = relu( naggH @ We2 ), K=64; staging patches col 63 = deg/degmax
__global__ __launch_bounds__(128) void k_gemm64(const float* __restrict__ A,
                                                const float* __restrict__ W,
                                                float* __restrict__ C, int n) {
    extern __shared__ float sm[];
    const int PITCH = 68;
    float* Ws  = sm;
    float* ins = sm + 64 * 64;
    int tid = threadIdx.x;
    int node0 = blockIdx.x * 128;
    float dmx = (float)max(g_degmax, 1);

    for (int idx = tid; idx < 64 * 16; idx += 128)
        ((float4*)Ws)[idx] = __ldg((const float4*)W + idx);
    for (int idx = tid; idx < 2048; idx += 128) {
        int r = idx >> 4, c4 = (idx & 15) << 2;
        int node = node0 + r;
        float4 va = make_float4(0.f, 0.f, 0.f, 0.f);
        if (node < n) {
            va = __ldg((const float4*)&A[(size_t)node * 64 + c4]);
            if (c4 == 60) va.w = (float)g_deg[node] / dmx;
        }
        *(float4*)&ins[r * PITCH + c4] = va;
    }
    __syncthreads();

    ull acc[8][4];
    gemm_core8x8<64, PITCH>(ins, Ws, acc);

    int q  = tid & 7;
    int rr = tid >> 3;
#pragma unroll
    for (int j = 0; j < 8; j++) {
        int node = node0 + rr + 16 * j;
        if (node < n) {
            float* Cr = &C[(size_t)node * 64 + q * 8];
            *(float4*)&Cr[0] = acc_relu4(acc[j][0], acc[j][1]);
            *(float4*)&Cr[4] = acc_relu4(acc[j][2], acc[j][3]);
        }
    }
}

// ------------------------------- readout -----------------------------------
__global__ void k_gconst(const float* __restrict__ Wp, const float* __restrict__ Wr,
                         const float* __restrict__ br) {
    int g = blockIdx.x;
    int t = threadIdx.x;
    __shared__ float m[64];
    __shared__ float red[64];
    float cnt = g_cnt[g];
    if (cnt <= 0.f) { if (t == 0) g_gconst[g] = 0.f; return; }
    m[t] = g_means[g * 64 + t] / cnt;
    __syncthreads();
    float p = 0.f;
#pragma unroll 8
    for (int k = 0; k < 64; k++) p += m[k] * __ldg(&Wp[k * 64 + t]);
    red[t] = fmaxf(p, 0.f) * __ldg(&Wr[t]);
    __syncthreads();
    if (t < 32) {
        float s = red[t] + red[t + 32];
#pragma unroll
        for (int off = 16; off > 0; off >>= 1) s += __shfl_down_sync(0xffffffffu, s, off);
        if (t == 0) g_gconst[g] = s + __ldg(&br[0]);
    }
}

__global__ void k_addg(const int* __restrict__ batch, float* __restrict__ out, int n) {
    int i = blockIdx.x * blockDim.x + threadIdx.x;
    if (i < n) out[i] += g_gconst[__ldg(&batch[i])];
}

// ---------------------------------------------------------------------------
extern "C" void kernel_launch(void* const* d_in, const int* in_sizes, int n_in,
                              void* d_out, int out_size) {
    const float* x    = (const float*)d_in[0];
    const float* Wi   = (const float*)d_in[1];
    const float* We1  = (const float*)d_in[2];
    const float* We2  = (const float*)d_in[3];
    const float* Wmsg = (const float*)d_in[4];
    const float* Wupd = (const float*)d_in[5];
    const float* Wp   = (const float*)d_in[6];
    const float* Wr   = (const float*)d_in[7];
    const float* br   = (const float*)d_in[8];
    const int*   eidx = (const int*)d_in[9];
    const int*   batch= (const int*)d_in[10];

    int n    = in_sizes[10];
    int E    = in_sizes[9] / 2;
    int nobs = in_sizes[0] / n;
    int L    = in_sizes[4] / (128 * 64);
    const int* row = eidx;
    const int* col = eidx + E;
    float* out = (float*)d_out;

    float *curA, *curB, *hbuf, *nagg, *naggH, *eemb, *means, *cnt;
    int *deg, *degmax;
    cudaGetSymbolAddress((void**)&curA, g_curA);
    cudaGetSymbolAddress((void**)&curB, g_curB);
    cudaGetSymbolAddress((void**)&hbuf, g_h);
    cudaGetSymbolAddress((void**)&nagg, g_nagg);
    cudaGetSymbolAddress((void**)&naggH, g_naggH);
    cudaGetSymbolAddress((void**)&eemb, g_eemb);
    cudaGetSymbolAddress((void**)&means, g_means);
    cudaGetSymbolAddress((void**)&cnt,   g_cnt);
    cudaGetSymbolAddress((void**)&deg,   g_deg);
    cudaGetSymbolAddress((void**)&degmax, g_degmax);

    const int SMEM_MMA = (512 * 16 + 128 * MSGP) * 4;   // 32KB Bf + 34KB msgbuf = 67584
    const int SMEM64   = (64 * 64 + 128 * 68) * 4;
    cudaFuncSetAttribute(k_layer_mma<false>, cudaFuncAttributeMaxDynamicSharedMemorySize, SMEM_MMA);
    cudaFuncSetAttribute(k_layer_mma<true>,  cudaFuncAttributeMaxDynamicSharedMemorySize, SMEM_MMA);
    cudaFuncSetAttribute(k_layer_mma<false>, cudaFuncAttributePreferredSharedMemoryCarveout, 100);
    cudaFuncSetAttribute(k_layer_mma<true>,  cudaFuncAttributePreferredSharedMemoryCarveout, 100);
    cudaFuncSetAttribute(k_gemm64, cudaFuncAttributeMaxDynamicSharedMemorySize, SMEM64);

    int gFI = (E + n * 64 + 255) / 256;
    int gHW = (n * 16 + 255) / 256;
    int gG  = (n + 127) / 128;
    int gA  = (n + 255) / 256;

    cudaMemsetAsync(deg,    0, (size_t)n * sizeof(int));
    cudaMemsetAsync(degmax, 0, sizeof(int));
    cudaMemsetAsync(means,  0, (size_t)MAXG * FD * sizeof(float));
    cudaMemsetAsync(cnt,    0, (size_t)MAXG * sizeof(float));

    k_fillpad<<<gFI, 256>>>(row, col, x, Wi, We1, E, n, nobs);   // kernel 1
    k_dgather<<<gHW, 256>>>(hbuf, curA, naggH, nagg, n);         // kernel 2
    k_gemm64<<<gG, 128, SMEM64>>>(naggH, We2, eemb, n);          // kernel 3

    float* cin = curA;
    float* cout = curB;
    for (int l = 0; l < L; l++) {
        bool last = (l == L - 1);
        if (l > 0) k_gather<<<gHW, 256>>>(cin, nagg, n);
        if (!last) {
            k_layer_mma<false><<<gG, 256, SMEM_MMA>>>(nagg, eemb, cin,   // kernel 4 (l=0): profiled
                                                      Wmsg + (size_t)l * 8192,
                                                      Wupd + (size_t)l * 8192,
                                                      cout, nullptr, nullptr, nullptr, n);
            float* tmp = cin; cin = cout; cout = tmp;
        } else {
            k_layer_mma<true><<<gG, 256, SMEM_MMA>>>(nagg, eemb, cin,
                                                     Wmsg + (size_t)l * 8192,
                                                     Wupd + (size_t)l * 8192,
                                                     nullptr, Wr, batch, out, n);
        }
    }

    k_gconst<<<MAXG, 64>>>(Wp, Wr, br);
    k_addg<<<gA, 256>>>(batch, out, n);
}